// round 12
// baseline (speedup 1.0000x reference)
#include <cuda_runtime.h>
#include <cuda_bf16.h>
#include <stdint.h>
#include <math.h>

// ---------------- fixed problem dimensions ----------------
#define Bb      4
#define Ss      2048
#define HIDDEN  512
#define Hh      8
#define HD      64
#define CHK     64
#define NCHK    32
#define BHN     32
#define MROWS   8192
#define NQKV    2048
#define K2      1024         // stored split width: [hi(512) | lo(512)]
#define NCHUNKS 24           // effective K' = 1536 over 64-wide chunks
#define SST     72           // smem row stride (elements), 144B

// ---------------- device scratch ----------------
__device__ __nv_bfloat16 g_Ap[MROWS * K2];     // [m][Ah|Al]
__device__ __nv_bfloat16 g_Bt[NQKV * K2];      // [n][Bh|Bl]
__device__ __nv_bfloat16 g_Zp[MROWS * K2];     // gated/normed Z split
__device__ __nv_bfloat16 g_WOt[HIDDEN * K2];   // [n][Bh|Bl]
__device__ float g_Q[BHN * Ss * HD];
__device__ float g_K[BHN * Ss * HD];
__device__ float g_V[BHN * Ss * HD];
__device__ float g_gate[MROWS * HIDDEN];
__device__ float g_Y[BHN * Ss * HD];
__device__ float g_Y2[BHN * Ss * HD];
__device__ float g_sq[Ss * 32];
__device__ float g_cq[Ss * 32];
__device__ float g_sk[Ss * 32];
__device__ float g_ck[Ss * 32];

// ---------------- PTX helpers ----------------
__device__ __forceinline__ uint32_t smem_u32(const void* p) {
    uint32_t a;
    asm("{ .reg .u64 t; cvta.to.shared.u64 t, %1; cvt.u32.u64 %0, t; }" : "=r"(a) : "l"(p));
    return a;
}
__device__ __forceinline__ void ldsm_x4(uint32_t& r0, uint32_t& r1, uint32_t& r2, uint32_t& r3,
                                        uint32_t addr) {
    asm volatile("ldmatrix.sync.aligned.m8n8.x4.shared.b16 {%0,%1,%2,%3}, [%4];"
                 : "=r"(r0), "=r"(r1), "=r"(r2), "=r"(r3) : "r"(addr));
}
__device__ __forceinline__ void mma16816(float* d, const uint32_t* a, const uint32_t* b) {
    asm volatile("mma.sync.aligned.m16n8k16.row.col.f32.bf16.bf16.f32 "
                 "{%0,%1,%2,%3}, {%4,%5,%6,%7}, {%8,%9}, {%0,%1,%2,%3};"
                 : "+f"(d[0]), "+f"(d[1]), "+f"(d[2]), "+f"(d[3])
                 : "r"(a[0]), "r"(a[1]), "r"(a[2]), "r"(a[3]), "r"(b[0]), "r"(b[1]));
}
__device__ __forceinline__ void cpasync16(uint32_t dst, const void* src) {
    asm volatile("cp.async.cg.shared.global [%0], [%1], 16;" :: "r"(dst), "l"(src) : "memory");
}
#define CP_COMMIT() asm volatile("cp.async.commit_group;" ::: "memory")
#define CP_WAIT1()  asm volatile("cp.async.wait_group 1;" ::: "memory")
#define CP_WAIT0()  asm volatile("cp.async.wait_group 0;" ::: "memory")

#define BUFA_BYTES 18432                 // 128*72*2
#define BUF_BYTES  (2 * BUFA_BYTES)
#define GEMM_SMEM  (2 * BUF_BYTES)

// ---------------- xPos factor tables ----------------
__global__ void xpos_tables() {
    int idx = blockIdx.x * blockDim.x + threadIdx.x;
    if (idx >= Ss * 32) return;
    int pos = idx >> 5, t = idx & 31;
    float inv_freq = (float)pow(10000.0, -(double)t / 32.0);
    float ang_f = (float)((double)pos * (double)inv_freq);
    double sn = sin((double)ang_f);
    double cs = cos((double)ang_f);
    float sbase = ((float)(2 * t) + 25.6f) / 89.6f;
    float scf = (float)pow((double)sbase, (double)pos / 512.0);
    float snf = (float)sn, csf = (float)cs;
    g_sq[idx] = snf * scf;
    g_cq[idx] = csf * scf;
    float iscf = 1.0f / scf;
    g_sk[idx] = snf * iscf;
    g_ck[idx] = csf * iscf;
}

// ---------------- split conversions ----------------
__device__ __forceinline__ void split_bf16(float x, __nv_bfloat16& h, __nv_bfloat16& l) {
    h = __float2bfloat16(x);
    l = __float2bfloat16(x - __bfloat162float(h));
}

__global__ void conv_x(const float* __restrict__ X) {
    int idx = blockIdx.x * blockDim.x + threadIdx.x;
    if (idx >= MROWS * HIDDEN) return;
    int m = idx >> 9, k = idx & 511;
    __nv_bfloat16 h, l;
    split_bf16(X[idx], h, l);
    size_t base = (size_t)m * K2;
    g_Ap[base + k] = h;
    g_Ap[base + 512 + k] = l;
}

__global__ void conv_w_proj(const float* __restrict__ WQ, const float* __restrict__ WK,
                            const float* __restrict__ WV, const float* __restrict__ WG) {
    int idx = blockIdx.x * blockDim.x + threadIdx.x;
    if (idx >= HIDDEN * NQKV) return;
    int k = idx / NQKV, j = idx - k * NQKV;
    int t = j >> 9, c = j & 511, n = c >> 6, d = c & 63;
    float v;
    if (t == 0)      v = WQ[(n * HIDDEN + k) * HD + d];
    else if (t == 1) v = WK[(n * HIDDEN + k) * HD + d];
    else if (t == 2) v = WV[(n * HIDDEN + k) * HD + d];
    else             v = WG[k * HIDDEN + c];
    __nv_bfloat16 h, l;
    split_bf16(v, h, l);
    size_t base = (size_t)j * K2;
    g_Bt[base + k] = h;
    g_Bt[base + 512 + k] = l;
}

__global__ void conv_wo(const float* __restrict__ WO) {
    int idx = blockIdx.x * blockDim.x + threadIdx.x;
    if (idx >= HIDDEN * HIDDEN) return;
    int k = idx >> 9, n = idx & 511;
    __nv_bfloat16 h, l;
    split_bf16(WO[k * HIDDEN + n], h, l);
    size_t base = (size_t)n * K2;
    g_WOt[base + k] = h;
    g_WOt[base + 512 + k] = l;
}

// ---------------- HMMA bf16-split GEMM mainloop ----------------
// 24 effective chunks over [Ah|Al] x [Bh|Bl]; chunk base = (i&7)*64:
//   i in [0,8):   Ah x Bh
//   i in [8,16):  Al x Bh   (A side +512)
//   i in [16,24): Ah x Bl   (B side +512)
__device__ __forceinline__ void hmma_issue(const __nv_bfloat16* Ag, const __nv_bfloat16* Bg,
                                           uint32_t sb, int i, int b, int tid) {
    const int aoff = (i & 7) * 64 + ((i >= 8 && i < 16) ? 512 : 0);
    const int boff = (i & 7) * 64 + ((i >= 16) ? 512 : 0);
#pragma unroll
    for (int q = 0; q < 4; q++) {
        int idx = q * 256 + tid;
        int row = idx >> 3;
        int c8  = (idx & 7) * 8;
        uint32_t doff = sb + b * BUF_BYTES + (uint32_t)(row * SST + c8) * 2;
        cpasync16(doff, Ag + (size_t)row * K2 + aoff + c8);
        cpasync16(doff + BUFA_BYTES, Bg + (size_t)row * K2 + boff + c8);
    }
    CP_COMMIT();
}

__device__ __forceinline__ void hmma_compute(uint32_t sb, int b, int wm, int wn, int lane,
                                             float acc[4][4][4]) {
    const int lrow = lane & 15;
    const int lcol = (lane >> 4) * 8;
    uint32_t aBase = sb + b * BUF_BYTES + (uint32_t)((wm * 64 + lrow) * SST + lcol) * 2;
    uint32_t bBase = sb + b * BUF_BYTES + BUFA_BYTES + (uint32_t)((wn * 32 + lrow) * SST + lcol) * 2;
#pragma unroll
    for (int kk = 0; kk < 4; kk++) {
        uint32_t af[4][4];
#pragma unroll
        for (int mt = 0; mt < 4; mt++)
            ldsm_x4(af[mt][0], af[mt][1], af[mt][2], af[mt][3],
                    aBase + (uint32_t)(mt * 16 * SST + kk * 16) * 2);
        uint32_t bf[4][2];
#pragma unroll
        for (int np = 0; np < 2; np++) {
            uint32_t r0, r1, r2, r3;
            ldsm_x4(r0, r1, r2, r3, bBase + (uint32_t)(np * 16 * SST + kk * 16) * 2);
            bf[np * 2][0] = r0;     bf[np * 2][1] = r2;
            bf[np * 2 + 1][0] = r1; bf[np * 2 + 1][1] = r3;
        }
#pragma unroll
        for (int mt = 0; mt < 4; mt++)
#pragma unroll
            for (int nt = 0; nt < 4; nt++)
                mma16816(acc[mt][nt], af[mt], bf[nt]);
    }
}

__device__ __forceinline__ void hmma_mainloop(const __nv_bfloat16* Ab, const __nv_bfloat16* Bb2,
                                              int rowA, int colB, uint32_t sb,
                                              float acc[4][4][4]) {
    const int tid = threadIdx.x;
    const int wid = tid >> 5, lane = tid & 31;
    const int wm = wid >> 2, wn = wid & 3;
#pragma unroll
    for (int mt = 0; mt < 4; mt++)
#pragma unroll
        for (int nt = 0; nt < 4; nt++)
#pragma unroll
            for (int e = 0; e < 4; e++) acc[mt][nt][e] = 0.f;

    const __nv_bfloat16* Ag = Ab + (size_t)rowA * K2;
    const __nv_bfloat16* Bg = Bb2 + (size_t)colB * K2;

    hmma_issue(Ag, Bg, sb, 0, 0, tid);
    for (int i = 0; i < NCHUNKS; i++) {
        if (i + 1 < NCHUNKS) {
            hmma_issue(Ag, Bg, sb, i + 1, (i + 1) & 1, tid);
            CP_WAIT1();
        } else {
            CP_WAIT0();
        }
        __syncthreads();
        hmma_compute(sb, i & 1, wm, wn, lane, acc);
        __syncthreads();
    }
}

// ---------------- projection GEMM (HMMA) + xPos/silu epilogue ----------------
__global__ __launch_bounds__(256, 2) void gemm_proj_tc() {
    extern __shared__ char smem[];
    uint32_t sb = smem_u32(smem);
    const int tid = threadIdx.x;
    const int wid = tid >> 5, lane = tid & 31;
    const int wm = wid >> 2, wn = wid & 3;
    const int rowA = blockIdx.y * 128, colB = blockIdx.x * 128;

    float acc[4][4][4];
    hmma_mainloop(g_Ap, g_Bt, rowA, colB, sb, acc);

#pragma unroll
    for (int nt = 0; nt < 4; nt++) {
        int c = colB + wn * 32 + nt * 8 + (lane & 3) * 2;
        int t = c >> 9, cc = c & 511, hh = cc >> 6, d0 = cc & 63;
#pragma unroll
        for (int mt = 0; mt < 4; mt++) {
#pragma unroll
            for (int p = 0; p < 2; p++) {
                int r = rowA + wm * 64 + mt * 16 + (lane >> 2) + p * 8;
                int bbv = r >> 11, s = r & 2047;
                float x0 = acc[mt][nt][2 * p], x1 = acc[mt][nt][2 * p + 1];
                if (t <= 1) {
                    const float* stab = (t == 0) ? g_sq : g_sk;
                    const float* ctab = (t == 0) ? g_cq : g_ck;
                    int ti = s * 32 + (d0 >> 1);
                    float sn = stab[ti], cs = ctab[ti];
                    float2 o = make_float2(x0 * cs - x1 * sn, x1 * cs + x0 * sn);
                    float* dst = ((t == 0) ? g_Q : g_K) +
                                 ((size_t)(bbv * Hh + hh) * Ss + s) * HD + d0;
                    *(float2*)dst = o;
                } else if (t == 2) {
                    float* dst = g_V + ((size_t)(bbv * Hh + hh) * Ss + s) * HD + d0;
                    *(float2*)dst = make_float2(x0, x1);
                } else {
                    float* dst = g_gate + (size_t)r * HIDDEN + cc;
                    *(float2*)dst = make_float2(x0 / (1.f + expf(-x0)),
                                                x1 / (1.f + expf(-x1)));
                }
            }
        }
    }
}

// ---------------- output GEMM (HMMA) ----------------
__global__ __launch_bounds__(256, 2) void gemm_out_tc(float* __restrict__ out) {
    extern __shared__ char smem[];
    uint32_t sb = smem_u32(smem);
    const int tid = threadIdx.x;
    const int wid = tid >> 5, lane = tid & 31;
    const int wm = wid >> 2, wn = wid & 3;
    const int rowA = blockIdx.y * 128, colB = blockIdx.x * 128;

    float acc[4][4][4];
    hmma_mainloop(g_Zp, g_WOt, rowA, colB, sb, acc);

#pragma unroll
    for (int mt = 0; mt < 4; mt++)
#pragma unroll
        for (int p = 0; p < 2; p++) {
            int r = rowA + wm * 64 + mt * 16 + (lane >> 2) + p * 8;
#pragma unroll
            for (int nt = 0; nt < 4; nt++) {
                int c = colB + wn * 32 + nt * 8 + (lane & 3) * 2;
                *(float2*)(out + (size_t)r * HIDDEN + c) =
                    make_float2(acc[mt][nt][2 * p], acc[mt][nt][2 * p + 1]);
            }
        }
}

// ---------------- fused retention: cross (blocks 0..127) + intra (blocks 128..1151) ----------------
#define RET_SMEM_FLOATS (3 * 64 * 68 + 128)
#define RET_SMEM_BYTES  (RET_SMEM_FLOATS * 4)

__device__ void retention_cross_body(float* sm) {
    float* Qt = sm;                    // 64*68
    float* Ks = sm + 64 * 68;          // 64*68
    float* Vs = sm + 2 * 64 * 68;      // 64*20
    float* Rs = Vs + 64 * 20;          // 64*20

    const int bh  = blockIdx.x >> 2;
    const int qtr = blockIdx.x & 3;
    const int h   = bh & 7;
    const int tid = threadIdx.x;
    const int tx  = tid & 15, ty = tid >> 4;
    const int i0  = ty * 4;
    const int rr  = tid >> 2;
    const int g4  = (tid & 3) * 4;

    float lg0 = logf(1.0f / 32.0f);
    float lg1 = logf(1.0f / 512.0f);
    float lin = lg0 + (float)h * ((lg1 - lg0) / 7.0f);
    float gamma = 1.0f - expf(lin);
    double gd = (double)gamma;
    const float g64f = (float)pow(gd, 64.0);
    const float gq = (float)pow(gd, (double)rr);
    const float gk = (float)pow(gd, -(double)rr);

    for (int idx = tid; idx < 64 * 20; idx += 256) Rs[idx] = 0.f;

    const float* Qb = g_Q + (size_t)bh * Ss * HD;
    const float* Kb = g_K + (size_t)bh * Ss * HD;
    const float* Vb = g_V + (size_t)bh * Ss * HD;
    float* Yb = g_Y2 + (size_t)bh * Ss * HD;

    float4 pq[4], pk[4], pv;
#pragma unroll
    for (int u = 0; u < 4; u++) {
        int c4 = g4 + u * 16;
        pq[u] = *(const float4*)(Qb + rr * HD + c4);
        pk[u] = *(const float4*)(Kb + rr * HD + c4);
    }
    pv = *(const float4*)(Vb + rr * HD + qtr * 16 + g4);
    __syncthreads();

    for (int qc = 0; qc < NCHK; qc++) {
#pragma unroll
        for (int u = 0; u < 4; u++) {
            int c4 = g4 + u * 16;
            Qt[(c4 + 0) * 68 + rr] = pq[u].x * gq;
            Qt[(c4 + 1) * 68 + rr] = pq[u].y * gq;
            Qt[(c4 + 2) * 68 + rr] = pq[u].z * gq;
            Qt[(c4 + 3) * 68 + rr] = pq[u].w * gq;
            *(float4*)(Ks + rr * 68 + c4) =
                make_float4(pk[u].x * gk, pk[u].y * gk, pk[u].z * gk, pk[u].w * gk);
        }
        *(float4*)(Vs + rr * 20 + g4) = pv;
        __syncthreads();

        if (qc + 1 < NCHK) {
            const float* Qg = Qb + (size_t)(qc + 1) * CHK * HD;
            const float* Kg = Kb + (size_t)(qc + 1) * CHK * HD;
            const float* Vg = Vb + (size_t)(qc + 1) * CHK * HD;
#pragma unroll
            for (int u = 0; u < 4; u++) {
                int c4 = g4 + u * 16;
                pq[u] = *(const float4*)(Qg + rr * HD + c4);
                pk[u] = *(const float4*)(Kg + rr * HD + c4);
            }
            pv = *(const float4*)(Vg + rr * HD + qtr * 16 + g4);
        }

        float o4[4] = {0.f, 0.f, 0.f, 0.f};
#pragma unroll 8
        for (int d = 0; d < 64; d++) {
            float4 q = *(float4*)(Qt + d * 68 + i0);
            float r = Rs[d * 20 + tx];
            o4[0] += q.x * r; o4[1] += q.y * r; o4[2] += q.z * r; o4[3] += q.w * r;
        }
        float* Yo = Yb + (size_t)(qc * CHK + i0) * HD + qtr * 16 + tx;
        Yo[0]      = o4[0];
        Yo[HD]     = o4[1];
        Yo[2 * HD] = o4[2];
        Yo[3 * HD] = o4[3];

        float c4a[4] = {0.f, 0.f, 0.f, 0.f};
#pragma unroll 8
        for (int j = 0; j < 64; j++) {
            float4 kk = *(float4*)(Ks + j * 68 + i0);
            float v = Vs[j * 20 + tx];
            c4a[0] += kk.x * v; c4a[1] += kk.y * v; c4a[2] += kk.z * v; c4a[3] += kk.w * v;
        }
        __syncthreads();
#pragma unroll
        for (int a = 0; a < 4; a++) {
            int off = (i0 + a) * 20 + tx;
            Rs[off] = g64f * (Rs[off] + c4a[a]);
        }
        __syncthreads();
    }
}

__device__ void retention_intra_body(float* sm, int blk) {
    float* Qt   = sm;
    float* Kt   = sm + 64 * 68;
    float* Vs   = sm + 2 * 64 * 68;
    float* gpos = sm + 3 * 64 * 68;

    const int bh = blk >> 5;
    const int qc = blk & 31;
    const int h  = bh & 7;
    const int tid = threadIdx.x;
    const int tx = tid & 15, ty = tid >> 4;
    const int i0 = ty * 4, j0 = tx * 4;
    const int rr = tid >> 2;
    const int g4 = (tid & 3) * 4;

    float lg0 = logf(1.0f / 32.0f);
    float lg1 = logf(1.0f / 512.0f);
    float lin = lg0 + (float)h * ((lg1 - lg0) / 7.0f);
    float gamma = 1.0f - expf(lin);
    double gd = (double)gamma;
    if (tid < 64) gpos[tid] = (float)pow(gd, (double)tid);

    const float* Qg = g_Q + ((size_t)bh * Ss + qc * CHK) * HD;
    const float* Kg = g_K + ((size_t)bh * Ss + qc * CHK) * HD;
    const float* Vg = g_V + ((size_t)bh * Ss + qc * CHK) * HD;
#pragma unroll
    for (int u = 0; u < 4; u++) {
        int c4 = g4 + u * 16;
        float4 q = *(const float4*)(Qg + rr * HD + c4);
        Qt[(c4 + 0) * 68 + rr] = q.x;
        Qt[(c4 + 1) * 68 + rr] = q.y;
        Qt[(c4 + 2) * 68 + rr] = q.z;
        Qt[(c4 + 3) * 68 + rr] = q.w;
        float4 k = *(const float4*)(Kg + rr * HD + c4);
        Kt[(c4 + 0) * 68 + rr] = k.x;
        Kt[(c4 + 1) * 68 + rr] = k.y;
        Kt[(c4 + 2) * 68 + rr] = k.z;
        Kt[(c4 + 3) * 68 + rr] = k.w;
        *(float4*)(Vs + rr * 68 + c4) = *(const float4*)(Vg + rr * HD + c4);
    }
    __syncthreads();

    float sv[4][4];
#pragma unroll
    for (int a = 0; a < 4; a++)
#pragma unroll
        for (int b = 0; b < 4; b++) sv[a][b] = 0.f;
#pragma unroll 8
    for (int d = 0; d < 64; d++) {
        float4 qa = *(float4*)(Qt + d * 68 + i0);
        float4 kb = *(float4*)(Kt + d * 68 + j0);
        float aq[4] = {qa.x, qa.y, qa.z, qa.w};
        float bk2[4] = {kb.x, kb.y, kb.z, kb.w};
#pragma unroll
        for (int a = 0; a < 4; a++)
#pragma unroll
            for (int b = 0; b < 4; b++) sv[a][b] += aq[a] * bk2[b];
    }
#pragma unroll
    for (int a = 0; a < 4; a++)
#pragma unroll
        for (int b = 0; b < 4; b++) {
            int e = (i0 + a) - (j0 + b);
            if (e < 0) e = -e;
            sv[a][b] *= gpos[e];
        }
    __syncthreads();
#pragma unroll
    for (int b = 0; b < 4; b++) {
        *(float4*)(Kt + (j0 + b) * 68 + i0) =
            make_float4(sv[0][b], sv[1][b], sv[2][b], sv[3][b]);
    }
    __syncthreads();

    float o[4][4];
#pragma unroll
    for (int a = 0; a < 4; a++)
#pragma unroll
        for (int b = 0; b < 4; b++) o[a][b] = 0.f;
#pragma unroll 8
    for (int j = 0; j < 64; j++) {
        float4 s4 = *(float4*)(Kt + j * 68 + i0);
        float4 vv = *(float4*)(Vs + j * 68 + j0);
        float as[4] = {s4.x, s4.y, s4.z, s4.w};
        float bv[4] = {vv.x, vv.y, vv.z, vv.w};
#pragma unroll
        for (int a = 0; a < 4; a++)
#pragma unroll
            for (int b = 0; b < 4; b++) o[a][b] += as[a] * bv[b];
    }

    float* Yg = g_Y + ((size_t)bh * Ss + qc * CHK) * HD;
#pragma unroll
    for (int a = 0; a < 4; a++)
        *(float4*)(Yg + (i0 + a) * HD + j0) = make_float4(o[a][0], o[a][1], o[a][2], o[a][3]);
}

__global__ __launch_bounds__(256) void retention_fused() {
    extern __shared__ float sm[];
    if (blockIdx.x < BHN * 4) retention_cross_body(sm);
    else                      retention_intra_body(sm, blockIdx.x - BHN * 4);
}

// ---------------- groupnorm + gate, emits 2-copy bf16 split Z ----------------
__global__ __launch_bounds__(256) void gn_gate(const float* __restrict__ gnw,
                                               const float* __restrict__ gnb) {
    int s = blockIdx.x, b = blockIdx.y;
    int tid = threadIdx.x;
    int h = tid >> 5, lane = tid & 31;
    const float* Yg  = g_Y  + ((size_t)(b * Hh + h) * Ss + s) * HD;
    const float* Y2g = g_Y2 + ((size_t)(b * Hh + h) * Ss + s) * HD;
    float y0 = Yg[lane]      + Y2g[lane];
    float y1 = Yg[lane + 32] + Y2g[lane + 32];
    float sum = y0 + y1, sq = y0 * y0 + y1 * y1;
#pragma unroll
    for (int off = 16; off; off >>= 1) {
        sum += __shfl_xor_sync(0xffffffffu, sum, off);
        sq  += __shfl_xor_sync(0xffffffffu, sq,  off);
    }
    float mu = sum * (1.f / 64.f);
    float var = sq * (1.f / 64.f) - mu * mu;
    float rstd = rsqrtf(var + 1e-5f);
    int r = b * Ss + s;
    int c0 = h * 64 + lane;
    float z0 = ((y0 - mu) * rstd * gnw[c0]      + gnb[c0])      * g_gate[(size_t)r * HIDDEN + c0];
    float z1 = ((y1 - mu) * rstd * gnw[c0 + 32] + gnb[c0 + 32]) * g_gate[(size_t)r * HIDDEN + c0 + 32];
    size_t base = (size_t)r * K2;
    __nv_bfloat16 h0, l0, h1, l1;
    split_bf16(z0, h0, l0);
    split_bf16(z1, h1, l1);
    g_Zp[base + c0]            = h0;
    g_Zp[base + 512 + c0]      = l0;
    g_Zp[base + c0 + 32]       = h1;
    g_Zp[base + 512 + c0 + 32] = l1;
}

// ---------------- launcher ----------------
extern "C" void kernel_launch(void* const* d_in, const int* in_sizes, int n_in,
                              void* d_out, int out_size) {
    const float* X   = (const float*)d_in[0];
    const float* WQ  = (const float*)d_in[1];
    const float* WK  = (const float*)d_in[2];
    const float* WV  = (const float*)d_in[3];
    const float* WG  = (const float*)d_in[4];
    const float* WO  = (const float*)d_in[5];
    const float* gnw = (const float*)d_in[6];
    const float* gnb = (const float*)d_in[7];
    float* out = (float*)d_out;
    (void)in_sizes; (void)n_in; (void)out_size;

    cudaFuncSetAttribute(retention_fused, cudaFuncAttributeMaxDynamicSharedMemorySize, RET_SMEM_BYTES);
    cudaFuncSetAttribute(gemm_proj_tc, cudaFuncAttributeMaxDynamicSharedMemorySize, GEMM_SMEM);
    cudaFuncSetAttribute(gemm_out_tc, cudaFuncAttributeMaxDynamicSharedMemorySize, GEMM_SMEM);

    xpos_tables<<<(Ss * 32 + 255) / 256, 256>>>();
    conv_w_proj<<<(HIDDEN * NQKV + 255) / 256, 256>>>(WQ, WK, WV, WG);
    conv_wo<<<(HIDDEN * HIDDEN + 255) / 256, 256>>>(WO);
    conv_x<<<(MROWS * HIDDEN + 255) / 256, 256>>>(X);
    gemm_proj_tc<<<dim3(NQKV / 128, MROWS / 128), 256, GEMM_SMEM>>>();
    retention_fused<<<BHN * 4 + NCHK * BHN, 256, RET_SMEM_BYTES>>>();
    gn_gate<<<dim3(Ss, Bb), 256>>>(gnw, gnb);
    gemm_out_tc<<<dim3(HIDDEN / 128, MROWS / 128), 256, GEMM_SMEM>>>(out);
}